// round 7
// baseline (speedup 1.0000x reference)
#include <cuda_runtime.h>
#include <cuda_fp16.h>
#include <cstdint>

#define NROWS 4096            // batch rows (2*2048)
#define NFEAT 16384           // 128*128
#define LDW 136               // W smem ld (fp16): 272B rows = 17*16B, ldmatrix conflict-free
#define LDB2 72               // B smem ld (fp16): 144B rows = 9*16B, ldmatrix conflict-free
#define DSTRIDE ((size_t)128 * 4096)
#define SMEM_BYTES ((128 * LDW + 128 * LDB2) * 2)   // 53248 B -> 3 CTAs/SM

// Scratch (allocation-free rule): ping-pong buffers (used as fp16) + W images.
__device__ float g_bufA[67108864];
__device__ float g_bufB[67108864];
__device__ __half g_wh[2][128 * 16384];   // fp16 W images, row-major [which][blk][n][k]

__device__ __forceinline__ void cp16(uint32_t d, const void* s) {
    asm volatile("cp.async.cg.shared.global [%0], [%1], 16;" :: "r"(d), "l"(s));
}
#define CP_COMMIT() asm volatile("cp.async.commit_group;" ::: "memory")
#define CP_WAIT0()  asm volatile("cp.async.wait_group 0;" ::: "memory")

// ---------------------------------------------------------------------------
// prep_w: L/R f32 -> fp16 row-major images
// ---------------------------------------------------------------------------
__global__ void prep_w_k(const float* __restrict__ L, const float* __restrict__ R) {
    const int which = blockIdx.y, blk = blockIdx.x, tid = threadIdx.x;
    const float* W = (which ? R : L) + (size_t)blk * 16384;
    __half* img = g_wh[which] + (size_t)blk * 16384;
#pragma unroll
    for (int it = 0; it < 16; ++it) {
        int idx = it * 256 + tid;            // 4096 float4s
        float4 v = *(const float4*)(W + idx * 4);
        __half* d = img + idx * 4;
        ((__half2*)d)[0] = __floats2half2_rn(v.x, v.y);
        ((__half2*)d)[1] = __floats2half2_rn(v.z, v.w);
    }
}

// ---------------------------------------------------------------------------
// T1: xt[c][r] (fp16) = x[r][c] (f32).  64x64 tiles.
// ---------------------------------------------------------------------------
__global__ void __launch_bounds__(256)
t1_k(__half* __restrict__ dst, const float* __restrict__ src) {
    __shared__ float t[64][65];
    const int c0 = blockIdx.x * 64, r0 = blockIdx.y * 64;
    const int tx = threadIdx.x & 15, ty = threadIdx.x >> 4;
#pragma unroll
    for (int k = 0; k < 4; ++k) {
        float4 v = *(const float4*)(src + (size_t)(r0 + ty + 16 * k) * NFEAT + c0 + 4 * tx);
        t[4 * tx + 0][ty + 16 * k] = v.x;
        t[4 * tx + 1][ty + 16 * k] = v.y;
        t[4 * tx + 2][ty + 16 * k] = v.z;
        t[4 * tx + 3][ty + 16 * k] = v.w;
    }
    __syncthreads();
#pragma unroll
    for (int k = 0; k < 4; ++k) {
        const int cl = ty + 16 * k;
        __half2 a = __floats2half2_rn(t[cl][4 * tx + 0], t[cl][4 * tx + 1]);
        __half2 b = __floats2half2_rn(t[cl][4 * tx + 2], t[cl][4 * tx + 3]);
        __half2* p = (__half2*)(dst + (size_t)(c0 + cl) * NROWS + r0 + 4 * tx);
        p[0] = a; p[1] = b;
    }
}

// ---------------------------------------------------------------------------
// T2: out[r][c] (f32) = out2[c][r] (fp16) + bias[c].  64x64 tiles.
// ---------------------------------------------------------------------------
__global__ void __launch_bounds__(256)
t2_k(float* __restrict__ dst, const __half* __restrict__ src,
     const float* __restrict__ bias) {
    __shared__ float t[64][65];
    __shared__ float bias_s[64];
    const int c0 = blockIdx.x * 64, r0 = blockIdx.y * 64;
    const int tx = threadIdx.x & 15, ty = threadIdx.x >> 4;
    if (threadIdx.x < 64) bias_s[threadIdx.x] = bias[c0 + threadIdx.x];
    __syncthreads();
#pragma unroll
    for (int k = 0; k < 4; ++k) {
        const int cl = ty + 16 * k;
        const __half2* p = (const __half2*)(src + (size_t)(c0 + cl) * NROWS + r0 + 4 * tx);
        __half2 a = p[0], b = p[1];
        const float bv = bias_s[cl];
        t[4 * tx + 0][cl] = __low2float(a)  + bv;
        t[4 * tx + 1][cl] = __high2float(a) + bv;
        t[4 * tx + 2][cl] = __low2float(b)  + bv;
        t[4 * tx + 3][cl] = __high2float(b) + bv;
    }
    __syncthreads();
#pragma unroll
    for (int k = 0; k < 4; ++k) {
        const int rl = ty + 16 * k;
        float4 w = make_float4(t[rl][4 * tx + 0], t[rl][4 * tx + 1],
                               t[rl][4 * tx + 2], t[rl][4 * tx + 3]);
        *(float4*)(dst + (size_t)(r0 + rl) * NFEAT + c0 + 4 * tx) = w;
    }
}

// ---------------------------------------------------------------------------
// MMA helpers
// ---------------------------------------------------------------------------
__device__ __forceinline__ void ldsm4(unsigned r[4], const __half* p) {
    unsigned a = (unsigned)__cvta_generic_to_shared(p);
    asm volatile("ldmatrix.sync.aligned.m8n8.x4.shared.b16 {%0,%1,%2,%3}, [%4];"
                 : "=r"(r[0]), "=r"(r[1]), "=r"(r[2]), "=r"(r[3]) : "r"(a));
}
__device__ __forceinline__ void ldsm4t(unsigned r[4], const __half* p) {
    unsigned a = (unsigned)__cvta_generic_to_shared(p);
    asm volatile("ldmatrix.sync.aligned.m8n8.x4.trans.shared.b16 {%0,%1,%2,%3}, [%4];"
                 : "=r"(r[0]), "=r"(r[1]), "=r"(r[2]), "=r"(r[3]) : "r"(a));
}
__device__ __forceinline__ void mma16816(float c[4], const unsigned a[4],
                                         unsigned b0, unsigned b1) {
    asm volatile("mma.sync.aligned.m16n8k16.row.col.f32.f16.f16.f32 "
                 "{%0,%1,%2,%3}, {%4,%5,%6,%7}, {%8,%9}, {%0,%1,%2,%3};"
                 : "+f"(c[0]), "+f"(c[1]), "+f"(c[2]), "+f"(c[3])
                 : "r"(a[0]), "r"(a[1]), "r"(a[2]), "r"(a[3]), "r"(b0), "r"(b1));
}

// ---------------------------------------------------------------------------
// GEMM stage (fp16 I/O): D[n][r] = sum_k W[blk,n,k] * B[k][r]
//  stage 1: B rows = xt[(k*128+blk)],  stage 2: B rows = z[(blk*128+k)]
//  D rows = (n*128+blk).  CTA tile 128n x 64r, K=128 single-shot cp.async.
//  52KB smem + <=85 regs -> 3 CTAs/SM (24 warps) to hide HMMA/ldsm latency.
// ---------------------------------------------------------------------------
__global__ void __launch_bounds__(256, 3)
gemm_k(__half* __restrict__ dst, const __half* __restrict__ bsrc,
       const __half* __restrict__ wimg, int stage) {
    extern __shared__ __half sh[];
    __half* wsm = sh;                 // [128 n][LDW]
    __half* bsm = sh + 128 * LDW;     // [128 k][LDB2]

    const int blk = blockIdx.y;
    const int r0  = blockIdx.x * 64;
    const int tid = threadIdx.x;

    const __half* wsrc = wimg + (size_t)blk * 16384;
    __half* D = dst + (size_t)blk * 4096;

    // ---- W: 128n x 128k, 2048 x 16B cp.async (8 per thread)
    {
        const uint32_t wb = (uint32_t)__cvta_generic_to_shared(wsm);
#pragma unroll
        for (int it = 0; it < 8; ++it) {
            int idx = it * 256 + tid;
            int n = idx >> 4, q = idx & 15;
            cp16(wb + (uint32_t)(n * LDW + q * 8) * 2, wsrc + n * 128 + q * 8);
        }
    }
    // ---- B: 128k x 64r, 1024 x 16B cp.async (4 per thread)
    {
        const uint32_t bb = (uint32_t)__cvta_generic_to_shared(bsm);
#pragma unroll
        for (int it = 0; it < 4; ++it) {
            int idx = it * 256 + tid;
            int k = idx >> 3, q = idx & 7;
            size_t grow = (stage == 1) ? ((size_t)k * 128 + blk)
                                       : ((size_t)blk * 128 + k);
            cp16(bb + (uint32_t)(k * LDB2 + q * 8) * 2,
                 bsrc + grow * 4096 + r0 + q * 8);
        }
    }
    CP_COMMIT();

    const int wid = tid >> 5, lane = tid & 31;
    const int wn = (wid & 3) * 32;     // n offset (4 warps over 128n)
    const int wr = (wid >> 2) * 32;    // r offset (2 warps over 64r)
    const int lrow  = lane & 15;
    const int lcol8 = (lane >> 4) << 3;

    float acc[2][4][4];
#pragma unroll
    for (int a = 0; a < 2; ++a)
#pragma unroll
        for (int b = 0; b < 4; ++b)
#pragma unroll
            for (int c = 0; c < 4; ++c) acc[a][b][c] = 0.0f;

    CP_WAIT0();
    __syncthreads();

#pragma unroll
    for (int k0 = 0; k0 < 128; k0 += 16) {
        unsigned Ah[2][4], Bh[2][4];
#pragma unroll
        for (int mt = 0; mt < 2; ++mt)
            ldsm4(Ah[mt], wsm + (wn + mt * 16 + lrow) * LDW + k0 + lcol8);
#pragma unroll
        for (int h = 0; h < 2; ++h)
            ldsm4t(Bh[h], bsm + (k0 + lrow) * LDB2 + wr + h * 16 + lcol8);
#pragma unroll
        for (int mt = 0; mt < 2; ++mt)
#pragma unroll
            for (int rt = 0; rt < 4; ++rt) {
                const int h = rt >> 1, p = (rt & 1) * 2;
                mma16816(acc[mt][rt], Ah[mt], Bh[h][p], Bh[h][p + 1]);
            }
    }

    // ---- epilogue: fp16 stores, rows (n*128+blk) strided DSTRIDE
    const int erow = lane >> 2;
    const int ecol = (lane & 3) * 2;
#pragma unroll
    for (int mt = 0; mt < 2; ++mt)
#pragma unroll
        for (int rt = 0; rt < 4; ++rt) {
            const int n0 = wn + mt * 16 + erow;
            const int rr = r0 + wr + rt * 8 + ecol;
            __half2 h01 = __floats2half2_rn(acc[mt][rt][0], acc[mt][rt][1]);
            __half2 h23 = __floats2half2_rn(acc[mt][rt][2], acc[mt][rt][3]);
            *(__half2*)(D + (size_t)n0 * DSTRIDE + rr)       = h01;
            *(__half2*)(D + (size_t)(n0 + 8) * DSTRIDE + rr) = h23;
        }
}

// ---------------------------------------------------------------------------
extern "C" void kernel_launch(void* const* d_in, const int* in_sizes, int n_in,
                              void* d_out, int out_size) {
    const float* x    = (const float*)d_in[0];
    const float* L    = (const float*)d_in[1];
    const float* R    = (const float*)d_in[2];
    const float* bias = (const float*)d_in[3];
    float* out = (float*)d_out;

    float *pA, *pB;
    cudaGetSymbolAddress((void**)&pA, g_bufA);
    cudaGetSymbolAddress((void**)&pB, g_bufB);
    __half* hA = (__half*)pA;
    __half* hB = (__half*)pB;
    __half* wh;
    cudaGetSymbolAddress((void**)&wh, g_wh);
    cudaFuncSetAttribute(gemm_k, cudaFuncAttributeMaxDynamicSharedMemorySize, SMEM_BYTES);

    // 0) weights -> fp16 row-major images
    prep_w_k<<<dim3(128, 2), 256>>>(L, R);
    // 1) xt[c][r] = fp16(x[r][c])
    t1_k<<<dim3(NFEAT / 64, NROWS / 64), 256>>>(hA, x);
    // 2) z[(n*128+b)][r] = fp16( sum_m L[b,n,m] * xt[(m*128+b)][r] )
    gemm_k<<<dim3(NROWS / 64, 128), 256, SMEM_BYTES>>>(hB, hA, wh, 1);
    // 3) out2[(i*128+j)][r] = fp16( sum_m R[j,i,m] * z[(j*128+m)][r] )
    gemm_k<<<dim3(NROWS / 64, 128), 256, SMEM_BYTES>>>(hA, hB, wh + (size_t)128 * 16384, 2);
    // 4) out[r][c] = out2[c][r] + bias[c]
    t2_k<<<dim3(NFEAT / 64, NROWS / 64), 256>>>(out, hA, bias);
}

// round 8
// speedup vs baseline: 1.0049x; 1.0049x over previous
#include <cuda_runtime.h>
#include <cuda_fp16.h>
#include <cstdint>

#define NROWS 4096            // batch rows (2*2048)
#define NFEAT 16384           // 128*128
#define LDWC 40               // W chunk smem ld (fp16): 80B rows, ldmatrix conflict-free
#define LDBC 136              // B chunk smem ld (fp16): 272B rows, ldmatrix conflict-free
#define DSTRIDE ((size_t)128 * 4096)
#define CH_W (128 * LDWC)     // halves per W chunk (128n x 32k +pad)
#define CH_B (32 * LDBC)      // halves per B chunk (32k x 128r +pad)
#define CH   (CH_W + CH_B)
#define SMEM_BYTES (2 * CH * 2)   // 2 stages, fp16 -> 37888 B -> 2 CTAs/SM

// Scratch (allocation-free rule): ping-pong buffers (used as fp16) + W images.
__device__ float g_bufA[67108864];
__device__ float g_bufB[67108864];
__device__ __half g_wh[2][128 * 16384];   // fp16 W images, row-major [which][blk][n][k]

__device__ __forceinline__ void cp16(uint32_t d, const void* s) {
    asm volatile("cp.async.cg.shared.global [%0], [%1], 16;" :: "r"(d), "l"(s));
}
#define CP_COMMIT() asm volatile("cp.async.commit_group;" ::: "memory")
#define CP_WAIT(n)  asm volatile("cp.async.wait_group %0;" :: "n"(n) : "memory")

// ---------------------------------------------------------------------------
// prep_w: L/R f32 -> fp16 row-major images
// ---------------------------------------------------------------------------
__global__ void prep_w_k(const float* __restrict__ L, const float* __restrict__ R) {
    const int which = blockIdx.y, blk = blockIdx.x, tid = threadIdx.x;
    const float* W = (which ? R : L) + (size_t)blk * 16384;
    __half* img = g_wh[which] + (size_t)blk * 16384;
#pragma unroll
    for (int it = 0; it < 16; ++it) {
        int idx = it * 256 + tid;            // 4096 float4s
        float4 v = *(const float4*)(W + idx * 4);
        __half* d = img + idx * 4;
        ((__half2*)d)[0] = __floats2half2_rn(v.x, v.y);
        ((__half2*)d)[1] = __floats2half2_rn(v.z, v.w);
    }
}

// ---------------------------------------------------------------------------
// T1: xt[c][r] (fp16) = x[r][c] (f32).  64x64 tiles.
// ---------------------------------------------------------------------------
__global__ void __launch_bounds__(256)
t1_k(__half* __restrict__ dst, const float* __restrict__ src) {
    __shared__ float t[64][65];
    const int c0 = blockIdx.x * 64, r0 = blockIdx.y * 64;
    const int tx = threadIdx.x & 15, ty = threadIdx.x >> 4;
#pragma unroll
    for (int k = 0; k < 4; ++k) {
        float4 v = *(const float4*)(src + (size_t)(r0 + ty + 16 * k) * NFEAT + c0 + 4 * tx);
        t[4 * tx + 0][ty + 16 * k] = v.x;
        t[4 * tx + 1][ty + 16 * k] = v.y;
        t[4 * tx + 2][ty + 16 * k] = v.z;
        t[4 * tx + 3][ty + 16 * k] = v.w;
    }
    __syncthreads();
#pragma unroll
    for (int k = 0; k < 4; ++k) {
        const int cl = ty + 16 * k;
        __half2 a = __floats2half2_rn(t[cl][4 * tx + 0], t[cl][4 * tx + 1]);
        __half2 b = __floats2half2_rn(t[cl][4 * tx + 2], t[cl][4 * tx + 3]);
        __half2* p = (__half2*)(dst + (size_t)(c0 + cl) * NROWS + r0 + 4 * tx);
        p[0] = a; p[1] = b;
    }
}

// ---------------------------------------------------------------------------
// T2: out[r][c] (f32) = out2[c][r] (fp16) + bias[c].  64x64 tiles.
// ---------------------------------------------------------------------------
__global__ void __launch_bounds__(256)
t2_k(float* __restrict__ dst, const __half* __restrict__ src,
     const float* __restrict__ bias) {
    __shared__ float t[64][65];
    __shared__ float bias_s[64];
    const int c0 = blockIdx.x * 64, r0 = blockIdx.y * 64;
    const int tx = threadIdx.x & 15, ty = threadIdx.x >> 4;
    if (threadIdx.x < 64) bias_s[threadIdx.x] = bias[c0 + threadIdx.x];
    __syncthreads();
#pragma unroll
    for (int k = 0; k < 4; ++k) {
        const int cl = ty + 16 * k;
        const __half2* p = (const __half2*)(src + (size_t)(c0 + cl) * NROWS + r0 + 4 * tx);
        __half2 a = p[0], b = p[1];
        const float bv = bias_s[cl];
        t[4 * tx + 0][cl] = __low2float(a)  + bv;
        t[4 * tx + 1][cl] = __high2float(a) + bv;
        t[4 * tx + 2][cl] = __low2float(b)  + bv;
        t[4 * tx + 3][cl] = __high2float(b) + bv;
    }
    __syncthreads();
#pragma unroll
    for (int k = 0; k < 4; ++k) {
        const int rl = ty + 16 * k;
        float4 w = make_float4(t[rl][4 * tx + 0], t[rl][4 * tx + 1],
                               t[rl][4 * tx + 2], t[rl][4 * tx + 3]);
        *(float4*)(dst + (size_t)(r0 + rl) * NFEAT + c0 + 4 * tx) = w;
    }
}

// ---------------------------------------------------------------------------
// MMA helpers
// ---------------------------------------------------------------------------
__device__ __forceinline__ void ldsm4(unsigned r[4], const __half* p) {
    unsigned a = (unsigned)__cvta_generic_to_shared(p);
    asm volatile("ldmatrix.sync.aligned.m8n8.x4.shared.b16 {%0,%1,%2,%3}, [%4];"
                 : "=r"(r[0]), "=r"(r[1]), "=r"(r[2]), "=r"(r[3]) : "r"(a));
}
__device__ __forceinline__ void ldsm4t(unsigned r[4], const __half* p) {
    unsigned a = (unsigned)__cvta_generic_to_shared(p);
    asm volatile("ldmatrix.sync.aligned.m8n8.x4.trans.shared.b16 {%0,%1,%2,%3}, [%4];"
                 : "=r"(r[0]), "=r"(r[1]), "=r"(r[2]), "=r"(r[3]) : "r"(a));
}
__device__ __forceinline__ void mma16816(float c[4], const unsigned a[4],
                                         unsigned b0, unsigned b1) {
    asm volatile("mma.sync.aligned.m16n8k16.row.col.f32.f16.f16.f32 "
                 "{%0,%1,%2,%3}, {%4,%5,%6,%7}, {%8,%9}, {%0,%1,%2,%3};"
                 : "+f"(c[0]), "+f"(c[1]), "+f"(c[2]), "+f"(c[3])
                 : "r"(a[0]), "r"(a[1]), "r"(a[2]), "r"(a[3]), "r"(b0), "r"(b1));
}

// ---------------------------------------------------------------------------
// GEMM stage (fp16 I/O): D[n][r] = sum_k W[blk,n,k] * B[k][r]
//  stage 1: B rows = xt[(k*128+blk)],  stage 2: B rows = z[(blk*128+k)]
//  D rows = (n*128+blk).  CTA tile 128n x 128r.
//  K in 4 chunks of 32, 2-stage cp.async double buffer (2 groups always in
//  flight) + 2 CTAs/SM: DRAM streaming overlaps HMMA continuously.
// ---------------------------------------------------------------------------
__global__ void __launch_bounds__(256, 2)
gemm_k(__half* __restrict__ dst, const __half* __restrict__ bsrc,
       const __half* __restrict__ wimg, int stage) {
    extern __shared__ __half sh[];

    const int blk = blockIdx.y;
    const int r0  = blockIdx.x * 128;
    const int tid = threadIdx.x;

    const __half* wsrc = wimg + (size_t)blk * 16384;
    __half* D = dst + (size_t)blk * 4096;
    const uint32_t shb = (uint32_t)__cvta_generic_to_shared(sh);

    // issue chunk c into stage s (B first: DRAM-bound; W is L2-hot)
    auto issue = [&](int c, int s) {
        const uint32_t bb = shb + (uint32_t)(s * CH + CH_W) * 2;
        const uint32_t wb = shb + (uint32_t)(s * CH) * 2;
#pragma unroll
        for (int it = 0; it < 2; ++it) {            // B: 32k x 128r
            int idx = it * 256 + tid;               // 512 x 16B
            int k = idx >> 4, q = idx & 15;
            int krow = c * 32 + k;
            size_t grow = (stage == 1) ? ((size_t)krow * 128 + blk)
                                       : ((size_t)blk * 128 + krow);
            cp16(bb + (uint32_t)(k * LDBC + q * 8) * 2,
                 bsrc + grow * 4096 + r0 + q * 8);
        }
#pragma unroll
        for (int it = 0; it < 2; ++it) {            // W: 128n x 32k
            int idx = it * 256 + tid;               // 512 x 16B
            int n = idx >> 2, q = idx & 3;
            cp16(wb + (uint32_t)(n * LDWC + q * 8) * 2,
                 wsrc + n * 128 + c * 32 + q * 8);
        }
        CP_COMMIT();
    };

    issue(0, 0);
    issue(1, 1);

    const int wid = tid >> 5, lane = tid & 31;
    const int wn = (wid & 1) * 64;     // n offset
    const int wr = (wid >> 1) * 32;    // r offset
    const int lrow  = lane & 15;
    const int lcol8 = (lane >> 4) << 3;

    float acc[4][4][4];
#pragma unroll
    for (int a = 0; a < 4; ++a)
#pragma unroll
        for (int b = 0; b < 4; ++b)
#pragma unroll
            for (int c = 0; c < 4; ++c) acc[a][b][c] = 0.0f;

#pragma unroll
    for (int c = 0; c < 4; ++c) {
        if (c == 3) { CP_WAIT(0); } else { CP_WAIT(1); }
        __syncthreads();
        const __half* wsm = sh + (c & 1) * CH;
        const __half* bsm = wsm + CH_W;
#pragma unroll
        for (int k0 = 0; k0 < 32; k0 += 16) {
            unsigned Ah[4][4], Bh[2][4];
#pragma unroll
            for (int mt = 0; mt < 4; ++mt)
                ldsm4(Ah[mt], wsm + (wn + mt * 16 + lrow) * LDWC + k0 + lcol8);
#pragma unroll
            for (int h = 0; h < 2; ++h)
                ldsm4t(Bh[h], bsm + (k0 + lrow) * LDBC + wr + h * 16 + lcol8);
#pragma unroll
            for (int mt = 0; mt < 4; ++mt)
#pragma unroll
                for (int rt = 0; rt < 4; ++rt) {
                    const int h = rt >> 1, p = (rt & 1) * 2;
                    mma16816(acc[mt][rt], Ah[mt], Bh[h][p], Bh[h][p + 1]);
                }
        }
        __syncthreads();                 // buffer consumed by all warps
        if (c + 2 < 4) issue(c + 2, c & 1);
    }

    // ---- epilogue: fp16 stores, rows (n*128+blk) strided DSTRIDE
    const int erow = lane >> 2;
    const int ecol = (lane & 3) * 2;
#pragma unroll
    for (int mt = 0; mt < 4; ++mt)
#pragma unroll
        for (int rt = 0; rt < 4; ++rt) {
            const int n0 = wn + mt * 16 + erow;
            const int rr = r0 + wr + rt * 8 + ecol;
            __half2 h01 = __floats2half2_rn(acc[mt][rt][0], acc[mt][rt][1]);
            __half2 h23 = __floats2half2_rn(acc[mt][rt][2], acc[mt][rt][3]);
            *(__half2*)(D + (size_t)n0 * DSTRIDE + rr)       = h01;
            *(__half2*)(D + (size_t)(n0 + 8) * DSTRIDE + rr) = h23;
        }
}

// ---------------------------------------------------------------------------
extern "C" void kernel_launch(void* const* d_in, const int* in_sizes, int n_in,
                              void* d_out, int out_size) {
    const float* x    = (const float*)d_in[0];
    const float* L    = (const float*)d_in[1];
    const float* R    = (const float*)d_in[2];
    const float* bias = (const float*)d_in[3];
    float* out = (float*)d_out;

    float *pA, *pB;
    cudaGetSymbolAddress((void**)&pA, g_bufA);
    cudaGetSymbolAddress((void**)&pB, g_bufB);
    __half* hA = (__half*)pA;
    __half* hB = (__half*)pB;
    __half* wh;
    cudaGetSymbolAddress((void**)&wh, g_wh);
    cudaFuncSetAttribute(gemm_k, cudaFuncAttributeMaxDynamicSharedMemorySize, SMEM_BYTES);

    // 0) weights -> fp16 row-major images
    prep_w_k<<<dim3(128, 2), 256>>>(L, R);
    // 1) xt[c][r] = fp16(x[r][c])
    t1_k<<<dim3(NFEAT / 64, NROWS / 64), 256>>>(hA, x);
    // 2) z[(n*128+b)][r] = fp16( sum_m L[b,n,m] * xt[(m*128+b)][r] )
    gemm_k<<<dim3(NROWS / 128, 128), 256, SMEM_BYTES>>>(hB, hA, wh, 1);
    // 3) out2[(i*128+j)][r] = fp16( sum_m R[j,i,m] * z[(j*128+m)][r] )
    gemm_k<<<dim3(NROWS / 128, 128), 256, SMEM_BYTES>>>(hA, hB, wh + (size_t)128 * 16384, 2);
    // 4) out[r][c] = out2[c][r] + bias[c]
    t2_k<<<dim3(NFEAT / 64, NROWS / 64), 256>>>(out, hA, bias);
}